// round 3
// baseline (speedup 1.0000x reference)
#include <cuda_runtime.h>
#include <cuda_bf16.h>
#include <cstdint>

// ----------------------------------------------------------------------------
// SpatialFeatureExtractor: 3x (conv1d k=3 pad=1 -> BN -> ReLU) + mean over L.
//   x: [1024, 520] fp32 -> h1: [1024,128,520] -> h2: [1024,256,520]
//   -> h3 reduced: out [1024,256] fp32 (mean over L)
// Round 3: resubmit of round-2 kernel (round 2 died to a container infra
// failure before compile/run). Fixes carried: A-tile ulonglong2 index j*33,
// 16B-aligned bf16 globals.
// ----------------------------------------------------------------------------

#define EPSV 1e-5f
constexpr int L  = 520;
constexpr int LP = 528;          // 1 left pad + 7 right pad (zeroed), 16B-aligned rows
constexpr int NS = 1024;         // samples (B*T)

__device__ __align__(16) __nv_bfloat16 g_h1[(size_t)NS * 128 * LP];   // ~138 MB
__device__ __align__(16) __nv_bfloat16 g_h2[(size_t)NS * 256 * LP];   // ~277 MB

// packed fp32x2 FMA: d = a*b + d, lanewise on 2 floats
__device__ __forceinline__ void dfma2(unsigned long long &d,
                                      unsigned long long a,
                                      unsigned long long b) {
    asm("fma.rn.f32x2 %0, %1, %2, %0;" : "+l"(d) : "l"(a), "l"(b));
}

// ----------------------------------------------------------------------------
// Kernel A: conv1 (Cin=1) + BN + ReLU -> g_h1 (bf16, padded rows)
// ----------------------------------------------------------------------------
__global__ void k_conv1(const float* __restrict__ x,  const float* __restrict__ w1,
                        const float* __restrict__ b1, const float* __restrict__ g1,
                        const float* __restrict__ be1, const float* __restrict__ m1,
                        const float* __restrict__ v1)
{
    __shared__ float xs[L + 2];          // +2 guard elems (never read with valid data)
    __shared__ __align__(16) __nv_bfloat16 hs[32 * LP];
    __shared__ float cw[128 * 3];
    __shared__ float ca[128], cb[128];

    const int tid = threadIdx.x;        // 256 threads
    const int n   = blockIdx.x;

    for (int i = tid; i < L; i += 256) xs[i] = x[(size_t)n * L + i];
    if (tid < 2) xs[L + tid] = 0.f;
    for (int i = tid; i < 128 * 3; i += 256) cw[i] = w1[i];
    if (tid < 128) {
        float a = g1[tid] * rsqrtf(v1[tid] + EPSV);
        ca[tid] = a;
        cb[tid] = (b1[tid] - m1[tid]) * a + be1[tid];
    }
    __syncthreads();

    for (int pass = 0; pass < 4; pass++) {
        const int cl  = tid >> 3;              // 0..31 local channel
        const int c   = pass * 32 + cl;        // global channel
        const int seg = tid & 7;               // 8 segs * 66 = 528 = LP
        const float w0 = cw[c * 3 + 0], wa = cw[c * 3 + 1], wb = cw[c * 3 + 2];
        const float a = ca[c], b = cb[c];
        for (int p = seg * 66; p < seg * 66 + 66; p++) {
            float v;
            if (p == 0 || p > L) {
                v = 0.f;                        // padded columns
            } else {
                int l = p - 1;
                float xm = (l > 0)     ? xs[l - 1] : 0.f;
                float xp = (l < L - 1) ? xs[l + 1] : 0.f;
                float y  = w0 * xm + wa * xs[l] + wb * xp;
                v = fmaxf(fmaf(y, a, b), 0.f);
            }
            hs[cl * LP + p] = __float2bfloat16(v);
        }
        __syncthreads();
        uint4*       dstv = reinterpret_cast<uint4*>(g_h1 + ((size_t)n * 128 + pass * 32) * LP);
        const uint4* srcv = reinterpret_cast<const uint4*>(hs);
        for (int i = tid; i < 32 * LP * 2 / 16; i += 256) dstv[i] = srcv[i];
        __syncthreads();
    }
}

// ----------------------------------------------------------------------------
// Kernel B: conv (CIN -> 256) + BN + ReLU as GEMM with 3 shifted taps.
//   FUSE=false : src = g_h1, dst = g_h2 (padded rows, pads zeroed here)
//   FUSE=true  : src = g_h2, fused mean -> out [1024,256]
// Tile: M=128 x N=104 (5 N-tiles cover 520). 256 thr: tm=tid&31 (4 M outputs =
// 2 f32x2 pairs, LDS.128 from A), tn=warp id (13 N outputs, broadcast LDS.64
// from duplicated {v,v} B tile).
// ----------------------------------------------------------------------------
template <int CIN, bool FUSE>
__global__ __launch_bounds__(256, 2)
void k_conv(const float* __restrict__ w,  const float* __restrict__ bb,
            const float* __restrict__ gg, const float* __restrict__ be,
            const float* __restrict__ mm, const float* __restrict__ vv,
            float* __restrict__ out)
{
    constexpr int CIN3 = CIN * 3;
    constexpr int KC   = 16;          // input channels per chunk
    constexpr int JC   = KC * 3;      // 48 K-indices per chunk
    constexpr int NT   = 104;         // N tile (520 = 5*104)
    constexpr int NWIN = NT + 2;      // B window incl. taps
    constexpr int BSTR = 108;         // padded B row stride (float2 units)
    constexpr int ASTR = 132;         // padded A row stride (floats, 16B-aligned pairs)

    __shared__ __align__(16) float  As[JC * ASTR];       // A tile: [j][c2]
    __shared__ __align__(16) float2 Bs[KC * BSTR];       // B tile, duplicated {v,v}
    __shared__ float s_alpha[128], s_beta[128], s_red[128];

    const int tid    = threadIdx.x;
    const int n      = blockIdx.x;
    const int c2base = blockIdx.y * 128;
    const int tm     = tid & 31;      // M group: local c2 = tm*4 + (0..3)
    const int tn     = tid >> 5;      // warp id = N group: local l = tn*13 + (0..12)

    const __nv_bfloat16* __restrict__ src = FUSE ? g_h2 : g_h1;
    __nv_bfloat16* dst = g_h2;

    if (tid < 128) {
        int c2g = c2base + tid;
        float a = gg[c2g] * rsqrtf(vv[c2g] + EPSV);
        s_alpha[tid] = a;
        s_beta[tid]  = (bb[c2g] - mm[c2g]) * a + be[c2g];
        if (FUSE) s_red[tid] = 0.f;
    }
    if (!FUSE) {
        // zero the pad columns of our 128 destination rows
        if (tid < 128) {
            __nv_bfloat16* row = dst + ((size_t)n * 256 + c2base + tid) * LP;
            __nv_bfloat16 z = __float2bfloat16(0.f);
            row[0] = z;
#pragma unroll
            for (int p = L + 1; p < LP; p++) row[p] = z;
        }
    }
    float msum[4];
    if (FUSE) { msum[0] = msum[1] = msum[2] = msum[3] = 0.f; }

    const unsigned long long* __restrict__ BsU  =
        reinterpret_cast<const unsigned long long*>(Bs);
    const ulonglong2* __restrict__ AsU2 =
        reinterpret_cast<const ulonglong2*>(As);

    for (int nt = 0; nt < 5; nt++) {
        const int l0 = nt * NT;
        unsigned long long acc[2][13];
#pragma unroll
        for (int mj = 0; mj < 2; mj++)
#pragma unroll
            for (int ni = 0; ni < 13; ni++) acc[mj][ni] = 0ull;

        for (int ch = 0; ch < CIN / KC; ch++) {
            __syncthreads();   // previous tile fully consumed
            // --- load A tile: As[j][c2] = w[(c2base+c2)*CIN3 + ch*JC + j] ---
            for (int i = tid; i < 128 * JC; i += 256) {
                int c2 = i / JC, j = i - c2 * JC;
                As[j * ASTR + c2] = w[(size_t)(c2base + c2) * CIN3 + ch * JC + j];
            }
            // --- load B tile (bf16 -> duplicated f32 pair) ---
            const __nv_bfloat16* sb = src + ((size_t)n * CIN + ch * KC) * LP + l0;
            for (int i = tid; i < KC * NWIN; i += 256) {
                int r = i / NWIN, col = i - r * NWIN;
                float v = __bfloat162float(sb[(size_t)r * LP + col]);
                Bs[r * BSTR + col] = make_float2(v, v);
            }
            __syncthreads();
            // --- compute ---
#pragma unroll 1
            for (int c1 = 0; c1 < KC; c1++) {
                unsigned long long rb[15];
#pragma unroll
                for (int wv = 0; wv < 15; wv++)
                    rb[wv] = BsU[c1 * BSTR + tn * 13 + wv];
#pragma unroll
                for (int t = 0; t < 3; t++) {
                    const int j = c1 * 3 + t;
                    ulonglong2 rav = AsU2[j * (ASTR / 4) + tm];   // row j at j*33
#pragma unroll
                    for (int ni = 0; ni < 13; ni++) {
                        dfma2(acc[0][ni], rav.x, rb[ni + t]);
                        dfma2(acc[1][ni], rav.y, rb[ni + t]);
                    }
                }
            }
        }

        // --- epilogue for this N tile ---
#pragma unroll
        for (int mj = 0; mj < 2; mj++) {
            const int c2l0 = tm * 4 + mj * 2;
            const float a0 = s_alpha[c2l0],     b0 = s_beta[c2l0];
            const float a1 = s_alpha[c2l0 + 1], b1 = s_beta[c2l0 + 1];
            if (!FUSE) {
                __nv_bfloat16* r0 = dst + ((size_t)n * 256 + c2base + c2l0) * LP
                                        + l0 + tn * 13 + 1;
                __nv_bfloat16* r1 = r0 + LP;
#pragma unroll
                for (int ni = 0; ni < 13; ni++) {
                    float lo = __uint_as_float((unsigned)(acc[mj][ni] & 0xffffffffu));
                    float hi = __uint_as_float((unsigned)(acc[mj][ni] >> 32));
                    r0[ni] = __float2bfloat16(fmaxf(fmaf(lo, a0, b0), 0.f));
                    r1[ni] = __float2bfloat16(fmaxf(fmaf(hi, a1, b1), 0.f));
                }
            } else {
                float s0 = 0.f, s1 = 0.f;
#pragma unroll
                for (int ni = 0; ni < 13; ni++) {
                    float lo = __uint_as_float((unsigned)(acc[mj][ni] & 0xffffffffu));
                    float hi = __uint_as_float((unsigned)(acc[mj][ni] >> 32));
                    s0 += fmaxf(fmaf(lo, a0, b0), 0.f);
                    s1 += fmaxf(fmaf(hi, a1, b1), 0.f);
                }
                msum[mj * 2 + 0] += s0;
                msum[mj * 2 + 1] += s1;
            }
        }
    }

    if (FUSE) {
        __syncthreads();
#pragma unroll
        for (int q = 0; q < 4; q++) atomicAdd(&s_red[tm * 4 + q], msum[q]);
        __syncthreads();
        if (tid < 128)
            out[(size_t)n * 256 + c2base + tid] = s_red[tid] * (1.f / 520.f);
    }
}

// ----------------------------------------------------------------------------
// launch
// ----------------------------------------------------------------------------
extern "C" void kernel_launch(void* const* d_in, const int* in_sizes, int n_in,
                              void* d_out, int out_size)
{
    (void)in_sizes; (void)n_in; (void)out_size;
    const float* x   = (const float*)d_in[0];
    const float* w1  = (const float*)d_in[1];
    const float* b1  = (const float*)d_in[2];
    const float* w2  = (const float*)d_in[3];
    const float* b2  = (const float*)d_in[4];
    const float* w3  = (const float*)d_in[5];
    const float* b3  = (const float*)d_in[6];
    const float* g1  = (const float*)d_in[7];
    const float* be1 = (const float*)d_in[8];
    const float* m1  = (const float*)d_in[9];
    const float* v1  = (const float*)d_in[10];
    const float* g2  = (const float*)d_in[11];
    const float* be2 = (const float*)d_in[12];
    const float* m2  = (const float*)d_in[13];
    const float* v2  = (const float*)d_in[14];
    const float* g3  = (const float*)d_in[15];
    const float* be3 = (const float*)d_in[16];
    const float* m3  = (const float*)d_in[17];
    const float* v3  = (const float*)d_in[18];
    float* out = (float*)d_out;

    k_conv1<<<NS, 256>>>(x, w1, b1, g1, be1, m1, v1);
    k_conv<128, false><<<dim3(NS, 2), 256>>>(w2, b2, g2, be2, m2, v2, nullptr);
    k_conv<256, true ><<<dim3(NS, 2), 256>>>(w3, b3, g3, be3, m3, v3, out);
}